// round 3
// baseline (speedup 1.0000x reference)
#include <cuda_runtime.h>
#include <math.h>
#include <stdint.h>

#define MU    0.02f
#define MU2   (MU * MU)
#define NBINS 10
#define NMAX  4194304
#define NBMAX 1024

// Scratch — __device__ globals (allocation-free rule).
__device__ float2       g_loss_buf[NMAX];             // (g, loss) per row, 32 MB
__device__ float        d_blk_min[NBMAX];
__device__ float        d_blk_max[NBMAX];
__device__ double       d_blk_loss[NBMAX][NBINS];
__device__ unsigned int d_blk_cnt[NBMAX][NBINS];
__device__ unsigned int d_bar;                        // monotonic barrier ticket (never reset)

// ---------------------------------------------------------------------------
// Software grid barrier: monotonic ticket counter, wrap-safe compare.
// Safe across graph replays (no reset needed). Requires all blocks resident.
__device__ __forceinline__ void grid_barrier() {
    __syncthreads();
    if (threadIdx.x == 0) {
        __threadfence();                                   // release phase writes
        unsigned int ticket = atomicAdd(&d_bar, 1u);
        unsigned int target = (ticket / gridDim.x + 1u) * gridDim.x;
        while ((int)(*(volatile unsigned int*)&d_bar - target) < 0) { }
        __threadfence();                                   // acquire remote writes
    }
    __syncthreads();
}

// Per-row math: rsqrt-based (MUFU.RSQ), ~2e-7 rel err, far under 1e-3 budget.
__device__ __forceinline__ float2 row_gl(float4 a, float4 b) {
    float d0 = a.x - b.x, d1 = a.y - b.y, d2 = a.z - b.z, d3 = a.w - b.w;
    float x0 = fmaf(d0, d0, MU2), x1 = fmaf(d1, d1, MU2);
    float x2 = fmaf(d2, d2, MU2), x3 = fmaf(d3, d3, MU2);
    float r0 = rsqrtf(x0), r1 = rsqrtf(x1), r2 = rsqrtf(x2), r3 = rsqrtf(x3);
    float loss = ((x0 * r0 - MU) + (x1 * r1 - MU)) + ((x2 * r2 - MU) + (x3 * r3 - MU));
    float g    = ((fabsf(d0) * r0 + fabsf(d1) * r1) + (fabsf(d2) * r2 + fabsf(d3) * r3));
    return make_float2(g, loss);
}

// ---------------------------------------------------------------------------
__global__ __launch_bounds__(256, 2)
void ghmr_fused(const float4* __restrict__ in, const float4* __restrict__ tg,
                float* __restrict__ out, int n) {
    const int tid    = blockIdx.x * blockDim.x + threadIdx.x;
    const int stride = gridDim.x * blockDim.x;
    const int lane   = threadIdx.x & 31;
    const int wid    = threadIdx.x >> 5;

    __shared__ float s_w0[8], s_w1[8];     // reused scratch for reductions
    __shared__ float s_range;

    // ===================== Phase A: g/loss + block min/max =====================
    float lmin = __int_as_float(0x7F800000);   // +inf
    float lmax = 0.0f;

    int i = tid;
    for (; i + 3 * stride < n; i += 4 * stride) {
        float4 a0 = in[i];              float4 b0 = tg[i];
        float4 a1 = in[i + stride];     float4 b1 = tg[i + stride];
        float4 a2 = in[i + 2 * stride]; float4 b2 = tg[i + 2 * stride];
        float4 a3 = in[i + 3 * stride]; float4 b3 = tg[i + 3 * stride];
        float2 v0 = row_gl(a0, b0); float2 v1 = row_gl(a1, b1);
        float2 v2 = row_gl(a2, b2); float2 v3 = row_gl(a3, b3);
        g_loss_buf[i]              = v0;
        g_loss_buf[i + stride]     = v1;
        g_loss_buf[i + 2 * stride] = v2;
        g_loss_buf[i + 3 * stride] = v3;
        lmin = fminf(fminf(fminf(lmin, v0.x), fminf(v1.x, v2.x)), v3.x);
        lmax = fmaxf(fmaxf(fmaxf(lmax, v0.x), fmaxf(v1.x, v2.x)), v3.x);
    }
    for (; i < n; i += stride) {
        float2 v = row_gl(in[i], tg[i]);
        g_loss_buf[i] = v;
        lmin = fminf(lmin, v.x);
        lmax = fmaxf(lmax, v.x);
    }

    #pragma unroll
    for (int o = 16; o > 0; o >>= 1) {
        lmin = fminf(lmin, __shfl_xor_sync(0xFFFFFFFFu, lmin, o));
        lmax = fmaxf(lmax, __shfl_xor_sync(0xFFFFFFFFu, lmax, o));
    }
    if (lane == 0) { s_w0[wid] = lmin; s_w1[wid] = lmax; }
    __syncthreads();
    if (wid == 0) {
        lmin = (lane < 8) ? s_w0[lane] : __int_as_float(0x7F800000);
        lmax = (lane < 8) ? s_w1[lane] : 0.0f;
        #pragma unroll
        for (int o = 4; o > 0; o >>= 1) {
            lmin = fminf(lmin, __shfl_xor_sync(0xFFFFFFFFu, lmin, o));
            lmax = fmaxf(lmax, __shfl_xor_sync(0xFFFFFFFFu, lmax, o));
        }
        if (lane == 0) {
            d_blk_min[blockIdx.x] = lmin;   // plain overwrite, no reset needed
            d_blk_max[blockIdx.x] = lmax;
        }
    }

    grid_barrier();

    // ============ All blocks reduce global min/max from block slots ============
    {
        float m = __int_as_float(0x7F800000), M = 0.0f;
        for (int r = threadIdx.x; r < (int)gridDim.x; r += blockDim.x) {
            m = fminf(m, d_blk_min[r]);
            M = fmaxf(M, d_blk_max[r]);
        }
        #pragma unroll
        for (int o = 16; o > 0; o >>= 1) {
            m = fminf(m, __shfl_xor_sync(0xFFFFFFFFu, m, o));
            M = fmaxf(M, __shfl_xor_sync(0xFFFFFFFFu, M, o));
        }
        __syncthreads();                // protect s_w0/s_w1 reuse
        if (lane == 0) { s_w0[wid] = m; s_w1[wid] = M; }
        __syncthreads();
        if (threadIdx.x == 0) {
            float gm = s_w0[0], gM = s_w1[0];
            #pragma unroll
            for (int w = 1; w < 8; w++) { gm = fminf(gm, s_w0[w]); gM = fmaxf(gM, s_w1[w]); }
            s_range = gM - gm;
        }
        __syncthreads();
    }
    const float range = s_range;

    // ================= Phase B: register histogram over scratch ================
    float        acc[NBINS];
    unsigned int cnt[NBINS];
    #pragma unroll
    for (int b = 0; b < NBINS; b++) { acc[b] = 0.0f; cnt[b] = 0u; }

    for (int j = tid; j < n; j += stride) {
        float2 v  = g_loss_buf[j];
        float  gn = v.x / range;                       // same op order as reference
        int    b  = (int)floorf(gn * (float)NBINS);
        b = min(max(b, 0), NBINS - 1);
        #pragma unroll
        for (int k = 0; k < NBINS; k++) {              // predicated select, no local mem
            if (k == b) { acc[k] += v.y; cnt[k]++; }
        }
    }

    // warp-reduce each bin, then cross-warp via smem, write per-block slots
    __shared__ float        s_acc[8][NBINS];
    __shared__ unsigned int s_cnt[8][NBINS];
    #pragma unroll
    for (int b = 0; b < NBINS; b++) {
        float        a = acc[b];
        unsigned int c = cnt[b];
        #pragma unroll
        for (int o = 16; o > 0; o >>= 1) {
            a += __shfl_xor_sync(0xFFFFFFFFu, a, o);
            c += __shfl_xor_sync(0xFFFFFFFFu, c, o);
        }
        if (lane == 0) { s_acc[wid][b] = a; s_cnt[wid][b] = c; }
    }
    __syncthreads();
    if (threadIdx.x < NBINS) {
        double       s = 0.0;
        unsigned int c = 0u;
        #pragma unroll
        for (int w = 0; w < 8; w++) { s += (double)s_acc[w][threadIdx.x]; c += s_cnt[w][threadIdx.x]; }
        d_blk_loss[blockIdx.x][threadIdx.x] = s;
        d_blk_cnt[blockIdx.x][threadIdx.x]  = c;
    }

    grid_barrier();

    // ======================= Phase C: block 0 finalizes =======================
    if (blockIdx.x == 0 && wid == 0) {
        double       s = 0.0;
        unsigned int c = 0u;
        if (lane < NBINS) {
            // 4 partial accumulators to break the fp64-add dependency chain
            double s0 = 0, s1 = 0, s2 = 0, s3 = 0;
            unsigned int c0 = 0, c1 = 0, c2 = 0, c3 = 0;
            int nb = (int)gridDim.x;
            int r = 0;
            for (; r + 3 < nb; r += 4) {
                s0 += d_blk_loss[r][lane];     c0 += d_blk_cnt[r][lane];
                s1 += d_blk_loss[r + 1][lane]; c1 += d_blk_cnt[r + 1][lane];
                s2 += d_blk_loss[r + 2][lane]; c2 += d_blk_cnt[r + 2][lane];
                s3 += d_blk_loss[r + 3][lane]; c3 += d_blk_cnt[r + 3][lane];
            }
            for (; r < nb; r++) { s0 += d_blk_loss[r][lane]; c0 += d_blk_cnt[r][lane]; }
            s = (s0 + s1) + (s2 + s3);
            c = (c0 + c1) + (c2 + c3);
        }
        double contrib = (c > 0u) ? s / (double)c : 0.0;   // 1 fp64 div per lane, parallel
        int    ne      = (c > 0u) ? 1 : 0;
        #pragma unroll
        for (int o = 16; o > 0; o >>= 1) {
            contrib += __shfl_xor_sync(0xFFFFFFFFu, contrib, o);
            ne      += __shfl_xor_sync(0xFFFFFFFFu, ne, o);
        }
        if (lane == 0) {
            if (ne < 1) ne = 1;
            out[0] = (float)(contrib / (double)ne / 64.0 / 4096.0);
        }
    }
}

// ---------------------------------------------------------------------------
extern "C" void kernel_launch(void* const* d_in, const int* in_sizes, int n_in,
                              void* d_out, int out_size) {
    const float4* in = (const float4*)d_in[0];
    const float4* tg = (const float4*)d_in[1];
    int n = in_sizes[0] / 4;           // rows (channels = 4)
    if (n > NMAX) n = NMAX;

    int sm = 0;
    if (cudaDeviceGetAttribute(&sm, cudaDevAttrMultiProcessorCount, 0) != cudaSuccess || sm <= 0)
        sm = 148;
    int nb = 2 * sm;                   // __launch_bounds__(256,2) guarantees co-residency
    if (nb > NBMAX) nb = NBMAX;

    ghmr_fused<<<nb, 256>>>(in, tg, (float*)d_out, n);
}

// round 4
// speedup vs baseline: 1.1028x; 1.1028x over previous
#include <cuda_runtime.h>
#include <math.h>
#include <stdint.h>

#define MU    0.02f
#define MU2   (MU * MU)
#define NBINS 10
#define NMAX  4194304
#define NBMAX 1024

// Scratch — __device__ globals (allocation-free rule).
__device__ float2       g_loss_buf[NMAX];             // (g, loss) per row, 32 MB
__device__ float        d_blk_min[NBMAX];
__device__ float        d_blk_max[NBMAX];
__device__ double       d_blk_loss[NBMAX][NBINS];
__device__ unsigned int d_blk_cnt[NBMAX][NBINS];
__device__ unsigned int d_bar;                        // monotonic barrier ticket (never reset)

// ---------------------------------------------------------------------------
// Software grid barrier: monotonic ticket counter, wrap-safe compare.
// Safe across graph replays (no reset needed). Requires all blocks resident.
__device__ __forceinline__ void grid_barrier() {
    __syncthreads();
    if (threadIdx.x == 0) {
        __threadfence();                                   // release phase writes
        unsigned int ticket = atomicAdd(&d_bar, 1u);
        unsigned int target = (ticket / gridDim.x + 1u) * gridDim.x;
        while ((int)(*(volatile unsigned int*)&d_bar - target) < 0) { }
        __threadfence();                                   // acquire remote writes
    }
    __syncthreads();
}

// Per-row math: rsqrt-based (MUFU.RSQ), ~2e-7 rel err, far under 1e-3 budget.
__device__ __forceinline__ float2 row_gl(float4 a, float4 b) {
    float d0 = a.x - b.x, d1 = a.y - b.y, d2 = a.z - b.z, d3 = a.w - b.w;
    float x0 = fmaf(d0, d0, MU2), x1 = fmaf(d1, d1, MU2);
    float x2 = fmaf(d2, d2, MU2), x3 = fmaf(d3, d3, MU2);
    float r0 = rsqrtf(x0), r1 = rsqrtf(x1), r2 = rsqrtf(x2), r3 = rsqrtf(x3);
    float loss = ((x0 * r0 - MU) + (x1 * r1 - MU)) + ((x2 * r2 - MU) + (x3 * r3 - MU));
    float g    = ((fabsf(d0) * r0 + fabsf(d1) * r1) + (fabsf(d2) * r2 + fabsf(d3) * r3));
    return make_float2(g, loss);
}

__device__ __forceinline__ float4 ldcs4(const float4* p) {
    return __ldcs(p);   // evict-first: don't pollute L2 (we want g_loss_buf resident)
}

// ---------------------------------------------------------------------------
__global__ __launch_bounds__(256, 4)
void ghmr_fused(const float4* __restrict__ in, const float4* __restrict__ tg,
                float* __restrict__ out, int n) {
    const int tid    = blockIdx.x * blockDim.x + threadIdx.x;
    const int stride = gridDim.x * blockDim.x;
    const int lane   = threadIdx.x & 31;
    const int wid    = threadIdx.x >> 5;

    __shared__ float s_w0[8], s_w1[8];     // reused scratch for reductions
    __shared__ float s_range;

    // ===================== Phase A: g/loss + block min/max =====================
    float lmin = __int_as_float(0x7F800000);   // +inf
    float lmax = 0.0f;

    int i = tid;
    for (; i + stride < n; i += 2 * stride) {
        float4 a0 = ldcs4(&in[i]);          float4 b0 = ldcs4(&tg[i]);
        float4 a1 = ldcs4(&in[i + stride]); float4 b1 = ldcs4(&tg[i + stride]);
        float2 v0 = row_gl(a0, b0);
        float2 v1 = row_gl(a1, b1);
        g_loss_buf[i]          = v0;
        g_loss_buf[i + stride] = v1;
        lmin = fminf(lmin, fminf(v0.x, v1.x));
        lmax = fmaxf(lmax, fmaxf(v0.x, v1.x));
    }
    for (; i < n; i += stride) {
        float2 v = row_gl(ldcs4(&in[i]), ldcs4(&tg[i]));
        g_loss_buf[i] = v;
        lmin = fminf(lmin, v.x);
        lmax = fmaxf(lmax, v.x);
    }

    #pragma unroll
    for (int o = 16; o > 0; o >>= 1) {
        lmin = fminf(lmin, __shfl_xor_sync(0xFFFFFFFFu, lmin, o));
        lmax = fmaxf(lmax, __shfl_xor_sync(0xFFFFFFFFu, lmax, o));
    }
    if (lane == 0) { s_w0[wid] = lmin; s_w1[wid] = lmax; }
    __syncthreads();
    if (wid == 0) {
        lmin = (lane < 8) ? s_w0[lane] : __int_as_float(0x7F800000);
        lmax = (lane < 8) ? s_w1[lane] : 0.0f;
        #pragma unroll
        for (int o = 4; o > 0; o >>= 1) {
            lmin = fminf(lmin, __shfl_xor_sync(0xFFFFFFFFu, lmin, o));
            lmax = fmaxf(lmax, __shfl_xor_sync(0xFFFFFFFFu, lmax, o));
        }
        if (lane == 0) {
            d_blk_min[blockIdx.x] = lmin;   // plain overwrite, no reset needed
            d_blk_max[blockIdx.x] = lmax;
        }
    }

    grid_barrier();

    // ============ All blocks reduce global min/max from block slots ============
    {
        float m = __int_as_float(0x7F800000), M = 0.0f;
        for (int r = threadIdx.x; r < (int)gridDim.x; r += blockDim.x) {
            m = fminf(m, d_blk_min[r]);
            M = fmaxf(M, d_blk_max[r]);
        }
        #pragma unroll
        for (int o = 16; o > 0; o >>= 1) {
            m = fminf(m, __shfl_xor_sync(0xFFFFFFFFu, m, o));
            M = fmaxf(M, __shfl_xor_sync(0xFFFFFFFFu, M, o));
        }
        __syncthreads();                // protect s_w0/s_w1 reuse
        if (lane == 0) { s_w0[wid] = m; s_w1[wid] = M; }
        __syncthreads();
        if (threadIdx.x == 0) {
            float gm = s_w0[0], gM = s_w1[0];
            #pragma unroll
            for (int w = 1; w < 8; w++) { gm = fminf(gm, s_w0[w]); gM = fmaxf(gM, s_w1[w]); }
            s_range = gM - gm;
        }
        __syncthreads();
    }
    const float range = s_range;

    // ================= Phase B: register histogram over scratch ================
    float        acc[NBINS];
    unsigned int cnt[NBINS];
    #pragma unroll
    for (int b = 0; b < NBINS; b++) { acc[b] = 0.0f; cnt[b] = 0u; }

    int j = tid;
    for (; j + stride < n; j += 2 * stride) {
        float2 v0 = g_loss_buf[j];
        float2 v1 = g_loss_buf[j + stride];
        int b0 = min(max((int)floorf((v0.x / range) * (float)NBINS), 0), NBINS - 1);
        int b1 = min(max((int)floorf((v1.x / range) * (float)NBINS), 0), NBINS - 1);
        #pragma unroll
        for (int k = 0; k < NBINS; k++) {              // predicated select, no local mem
            if (k == b0) { acc[k] += v0.y; cnt[k]++; }
            if (k == b1) { acc[k] += v1.y; cnt[k]++; }
        }
    }
    for (; j < n; j += stride) {
        float2 v = g_loss_buf[j];
        int b = min(max((int)floorf((v.x / range) * (float)NBINS), 0), NBINS - 1);
        #pragma unroll
        for (int k = 0; k < NBINS; k++) {
            if (k == b) { acc[k] += v.y; cnt[k]++; }
        }
    }

    // warp-reduce each bin, then cross-warp via smem, write per-block slots
    __shared__ float        s_acc[8][NBINS];
    __shared__ unsigned int s_cnt[8][NBINS];
    #pragma unroll
    for (int b = 0; b < NBINS; b++) {
        float        a = acc[b];
        unsigned int c = cnt[b];
        #pragma unroll
        for (int o = 16; o > 0; o >>= 1) {
            a += __shfl_xor_sync(0xFFFFFFFFu, a, o);
            c += __shfl_xor_sync(0xFFFFFFFFu, c, o);
        }
        if (lane == 0) { s_acc[wid][b] = a; s_cnt[wid][b] = c; }
    }
    __syncthreads();
    if (threadIdx.x < NBINS) {
        double       s = 0.0;
        unsigned int c = 0u;
        #pragma unroll
        for (int w = 0; w < 8; w++) { s += (double)s_acc[w][threadIdx.x]; c += s_cnt[w][threadIdx.x]; }
        d_blk_loss[blockIdx.x][threadIdx.x] = s;
        d_blk_cnt[blockIdx.x][threadIdx.x]  = c;
    }

    grid_barrier();

    // ======================= Phase C: block 0 finalizes =======================
    if (blockIdx.x == 0 && wid == 0) {
        double       s = 0.0;
        unsigned int c = 0u;
        if (lane < NBINS) {
            // 4 partial accumulators to break the fp64-add dependency chain
            double s0 = 0, s1 = 0, s2 = 0, s3 = 0;
            unsigned int c0 = 0, c1 = 0, c2 = 0, c3 = 0;
            int nb = (int)gridDim.x;
            int r = 0;
            for (; r + 3 < nb; r += 4) {
                s0 += d_blk_loss[r][lane];     c0 += d_blk_cnt[r][lane];
                s1 += d_blk_loss[r + 1][lane]; c1 += d_blk_cnt[r + 1][lane];
                s2 += d_blk_loss[r + 2][lane]; c2 += d_blk_cnt[r + 2][lane];
                s3 += d_blk_loss[r + 3][lane]; c3 += d_blk_cnt[r + 3][lane];
            }
            for (; r < nb; r++) { s0 += d_blk_loss[r][lane]; c0 += d_blk_cnt[r][lane]; }
            s = (s0 + s1) + (s2 + s3);
            c = (c0 + c1) + (c2 + c3);
        }
        double contrib = (c > 0u) ? s / (double)c : 0.0;   // 1 fp64 div per lane, parallel
        int    ne      = (c > 0u) ? 1 : 0;
        #pragma unroll
        for (int o = 16; o > 0; o >>= 1) {
            contrib += __shfl_xor_sync(0xFFFFFFFFu, contrib, o);
            ne      += __shfl_xor_sync(0xFFFFFFFFu, ne, o);
        }
        if (lane == 0) {
            if (ne < 1) ne = 1;
            out[0] = (float)(contrib / (double)ne / 64.0 / 4096.0);
        }
    }
}

// ---------------------------------------------------------------------------
extern "C" void kernel_launch(void* const* d_in, const int* in_sizes, int n_in,
                              void* d_out, int out_size) {
    const float4* in = (const float4*)d_in[0];
    const float4* tg = (const float4*)d_in[1];
    int n = in_sizes[0] / 4;           // rows (channels = 4)
    if (n > NMAX) n = NMAX;

    int sm = 0;
    if (cudaDeviceGetAttribute(&sm, cudaDevAttrMultiProcessorCount, 0) != cudaSuccess || sm <= 0)
        sm = 148;
    int nb = 4 * sm;                   // __launch_bounds__(256,4) guarantees co-residency
    if (nb > NBMAX) nb = NBMAX;

    ghmr_fused<<<nb, 256>>>(in, tg, (float*)d_out, n);
}